// round 5
// baseline (speedup 1.0000x reference)
#include <cuda_runtime.h>

#define NV 6
#define NT 3
#define NC 256
#define SP 1024
#define NHD 8
#define CHUNK 128
#define NB 144              // grid size; 1 CTA/SM (132KB smem) -> all co-resident
#define SCALE 0.17677669529663687f
#define LN_EPS 1e-5f
#define NSLOT 8

// ---------------- scratch ----------------------------------------------------
__device__ float g_wq[NC*NHD];          // [c*8+h]
__device__ float g_S8[NSLOT*NHD*NC];    // slotted unnormalized sum_k e*kv
__device__ float g_L8[NSLOT*NHD];       // slotted sum_k e
__device__ float g_t[NC];
__device__ float g_u[NC];
__device__ unsigned long long g_bar;    // monotonic grid-barrier counter

__device__ __forceinline__ float wredsum(float v){
#pragma unroll
    for(int o=16;o;o>>=1) v += __shfl_down_sync(0xffffffffu, v, o);
    return v;
}

// Grid barrier: monotonic counter, valid across graph replays (advances by
// exactly NB per barrier; all NB blocks are co-resident so no deadlock).
__device__ __forceinline__ void grid_barrier(){
    __syncthreads();
    __threadfence();                      // release prior writes
    if(threadIdx.x == 0){
        unsigned long long old = atomicAdd(&g_bar, 1ULL);
        unsigned long long target = old - (old % NB) + NB;
        for(;;){
            unsigned long long cur;
            asm volatile("ld.volatile.global.u64 %0, [%1];" : "=l"(cur) : "l"(&g_bar));
            if(cur >= target) break;
            __nanosleep(64);
        }
        __threadfence();                  // acquire
    }
    __syncthreads();
}

// ---------------- ONE fused kernel -------------------------------------------
__global__ __launch_bounds__(512,1)
void k_fused(const float* __restrict__ hf,  const float* __restrict__ qe,
             const float* __restrict__ cpe, const float* __restrict__ tpe,
             const float* __restrict__ spe, const float* __restrict__ qw,
             const float* __restrict__ qb,  const float* __restrict__ kw,
             const float* __restrict__ vw,  const float* __restrict__ vb,
             const float* __restrict__ ow,  const float* __restrict__ ob,
             const float* __restrict__ lng, const float* __restrict__ lnb,
             const int*   __restrict__ qidx_p,
             float* __restrict__ out){
    extern __shared__ float tile[];               // [256][129], 132096 B
    __shared__ float pe[NC];
    __shared__ __align__(16) float wq_sm[NC*NHD];
    __shared__ __align__(16) float p_sm[CHUNK*NHD];     // [pos*8+h]
    __shared__ float sred[4*NHD*CHUNK];                 // [q][h][pos]
    __shared__ __align__(16) float S_sm[NC];
    __shared__ float red16[16];
    __shared__ float u_sm[NC];
    __shared__ float r1[16], r2[16];

    int tid = threadIdx.x;
    int b = blockIdx.x;
    int w = tid >> 5, ln = tid & 31;

    // ================= P0: prep (blocks 0..7 wq, 8..15 zero slots) ===========
    if(b < 8){
        int h = b;
        if(tid < 256){
            int qidx = qidx_p ? qidx_p[0] : 0;
            S_sm[tid] = qe[tid] + cpe[qidx*NC + tid] + spe[tid];   // reuse S_sm as qv
        }
        __syncthreads();
        if(w < 8){
            const float4* qv4 = (const float4*)S_sm;
            float4 x = qv4[ln*2], y = qv4[ln*2+1];
#pragma unroll
            for(int k=0;k<4;k++){
                int j = h*32 + w*4 + k;
                const float4* qwr = (const float4*)(qw + (size_t)j*NC);
                float4 a = qwr[ln*2], b4 = qwr[ln*2+1];
                float d = a.x*x.x + a.y*x.y + a.z*x.z + a.w*x.w
                        + b4.x*y.x + b4.y*y.y + b4.z*y.z + b4.w*y.w;
                d = wredsum(d);
                if(ln == 0) red16[0] = 0.f, u_sm[w*4+k] = d + qb[j];  // qp -> u_sm[0..31]
            }
        }
        __syncthreads();
        if(tid < 256){
            float acc = 0.f;
            const float* kwb = kw + (size_t)(h*32)*NC + tid;
#pragma unroll
            for(int d=0; d<32; d++) acc += u_sm[d]*kwb[(size_t)d*NC];
            g_wq[tid*NHD + h] = acc * SCALE;
        }
    } else if(b < 16){
        int z = b - 8;
#pragma unroll
        for(int i=0;i<4;i++) g_S8[z*2048 + i*512 + tid] = 0.f;
        if(tid < NHD) g_L8[z*NHD + tid] = 0.f;
    }
    grid_barrier();

    // ================= P1: main pass (proven body) ===========================
    {
        int vt = b >> 3, chunk = b & 7;
        int v = vt / NT, t = vt - v*NT;
        int pos = tid & 127, q = tid >> 7;      // q: channel quarter 0..3
        int c0 = q*64;

        if(tid < 256) pe[tid] = tpe[t*NC + tid] + cpe[v*NC + tid];
#pragma unroll
        for(int k=0;k<4;k++) wq_sm[tid + k*512] = __ldcg(&g_wq[tid + k*512]);
        __syncthreads();

        // stage kv tile: 64 channels/thread, 16 loads in flight
        {
            const float* src = hf + ((size_t)(vt*NC + c0))*SP + chunk*CHUNK + pos;
            float r[16];
#pragma unroll
            for(int bch=0; bch<4; bch++){
#pragma unroll
                for(int j=0;j<16;j++) r[j] = src[(size_t)(bch*16+j)*SP];
#pragma unroll
                for(int j=0;j<16;j++){
                    int c = c0 + bch*16 + j;
                    tile[c*129 + pos] = r[j] + pe[c];
                }
            }
        }
        __syncthreads();

        // pass 1: per-quarter score partials
        {
            float acc[8];
#pragma unroll
            for(int h=0;h<8;h++) acc[h]=0.f;
            const float4* wq4 = (const float4*)wq_sm;
#pragma unroll 4
            for(int i=0;i<64;i++){
                int c = c0 + i;
                float kv = tile[c*129 + pos];
                float4 w0 = wq4[c*2], w1 = wq4[c*2+1];
                acc[0] += kv*w0.x; acc[1] += kv*w0.y; acc[2] += kv*w0.z; acc[3] += kv*w0.w;
                acc[4] += kv*w1.x; acc[5] += kv*w1.y; acc[6] += kv*w1.z; acc[7] += kv*w1.w;
            }
#pragma unroll
            for(int h=0;h<8;h++) sred[q*1024 + h*128 + pos] = acc[h];
        }
        __syncthreads();

        // scores -> e = exp(s) (|s| << 1, no max shift), local l
        if(w < 8){
            float l = 0.f;
#pragma unroll
            for(int qq=0;qq<4;qq++){
                int p = ln + qq*32;
                float s = sred[w*128+p] + sred[1024+w*128+p]
                        + sred[2048+w*128+p] + sred[3072+w*128+p];
                float e = __expf(s);
                p_sm[p*8 + w] = e;
                l += e;
            }
            l = wredsum(l);
            if(ln == 0) atomicAdd(&g_L8[(b & (NSLOT-1))*NHD + w], l);
        }
        __syncthreads();

        // pass 2: partial[h][c] = sum_pos e*kv
        {
            int grp = tid >> 6, cid = tid & 63;
            float acc[8][4];
#pragma unroll
            for(int h=0;h<8;h++)
#pragma unroll
                for(int qq=0;qq<4;qq++) acc[h][qq]=0.f;
            const float4* p4 = (const float4*)p_sm;
            int p0 = grp*16;
#pragma unroll 2
            for(int pp=0;pp<16;pp++){
                int p = p0 + pp;
                float4 pa = p4[p*2], pb = p4[p*2+1];
                float pv[8] = {pa.x,pa.y,pa.z,pa.w,pb.x,pb.y,pb.z,pb.w};
                float kvv[4];
#pragma unroll
                for(int qq=0;qq<4;qq++) kvv[qq] = tile[(cid + qq*64)*129 + p];
#pragma unroll
                for(int h=0;h<8;h++)
#pragma unroll
                    for(int qq=0;qq<4;qq++) acc[h][qq] += pv[h]*kvv[qq];
            }
            __syncthreads();
#pragma unroll
            for(int h=0;h<8;h++)
#pragma unroll
                for(int qq=0;qq<4;qq++)
                    tile[grp*2048 + h*256 + (cid + qq*64)] = acc[h][qq];
        }
        __syncthreads();

        // combine 8 groups, slotted atomic accumulate
        {
            int slot = b & (NSLOT-1);
#pragma unroll
            for(int k=0;k<4;k++){
                int idx = k*512 + tid;
                float s = 0.f;
#pragma unroll
                for(int g=0; g<8; g++) s += tile[g*2048 + idx];
                atomicAdd(&g_S8[slot*2048 + idx], s);
            }
        }
    }
    grid_barrier();

    // ================= P2: t = V-GEMV (blocks 0..63, 4 rows each) ============
    if(b < 64){
        int h = b >> 3;
        if(tid < 256){
            float s = 0.f;
#pragma unroll
            for(int r=0;r<NSLOT;r++) s += __ldcg(&g_S8[r*2048 + h*256 + tid]);
            float L = 0.f;
#pragma unroll
            for(int r=0;r<NSLOT;r++) L += __ldcg(&g_L8[r*NHD + h]);
            S_sm[tid] = s / L;
        }
        __syncthreads();
        int r = tid >> 7, cid = tid & 127;
        int j = b*4 + r;
        float2 S2 = ((const float2*)S_sm)[cid];
        float2 w2 = ((const float2*)(vw + (size_t)j*NC))[cid];
        float part = S2.x*w2.x + S2.y*w2.y;
        part = wredsum(part);
        if(ln == 0) red16[w] = part;
        __syncthreads();
        if(tid < 4){
            float s = red16[tid*4] + red16[tid*4+1] + red16[tid*4+2] + red16[tid*4+3];
            g_t[b*4 + tid] = s + vb[b*4 + tid];
        }
    }
    grid_barrier();

    // ================= P3: u = O-GEMV (blocks 0..63, 4 rows each) ============
    if(b < 64){
        if(tid < 256) S_sm[tid] = __ldcg(&g_t[tid]);
        __syncthreads();
        int r = tid >> 7, cid = tid & 127;
        int j = b*4 + r;
        float2 S2 = ((const float2*)S_sm)[cid];
        float2 w2 = ((const float2*)(ow + (size_t)j*NC))[cid];
        float part = S2.x*w2.x + S2.y*w2.y;
        part = wredsum(part);
        if(ln == 0) red16[w] = part;
        __syncthreads();
        if(tid < 4){
            float s = red16[tid*4] + red16[tid*4+1] + red16[tid*4+2] + red16[tid*4+3];
            g_u[b*4 + tid] = s + ob[b*4 + tid];
        }
    }
    grid_barrier();

    // ================= P4: LayerNorm + broadcast (all 144 blocks) ============
    {
        float uv = (tid < 256) ? __ldcg(&g_u[tid]) : 0.f;
        if(tid < 256) u_sm[tid] = uv;
        float s1 = wredsum(uv);
        float s2 = wredsum(uv*uv);
        if(ln == 0){ r1[w] = s1; r2[w] = s2; }
        __syncthreads();
        if(w == 0){
            float a = (ln < 16) ? r1[ln] : 0.f;
            float bb = (ln < 16) ? r2[ln] : 0.f;
#pragma unroll
            for(int o=8;o;o>>=1){
                a += __shfl_down_sync(0xffffffffu,a,o);
                bb += __shfl_down_sync(0xffffffffu,bb,o);
            }
            if(ln == 0){ r1[0] = a; r2[0] = bb; }
        }
        __syncthreads();
        float mu  = r1[0] * (1.f/NC);
        float var = r2[0] * (1.f/NC) - mu*mu;
        float rstd = rsqrtf(var + LN_EPS);
        for(int c = b; c < 256; c += NB){
            float yv = (u_sm[c] - mu) * rstd * lng[c] + lnb[c];
            ((float2*)out)[c*512 + tid] = make_float2(yv, yv);
        }
    }
}

// ---------------- launch -----------------------------------------------------
extern "C" void kernel_launch(void* const* d_in, const int* in_sizes, int n_in,
                              void* d_out, int out_size){
    const float* hf  = (const float*)d_in[0];
    const float* qe  = (const float*)d_in[1];
    const float* cpe = (const float*)d_in[2];
    const float* tpe = (const float*)d_in[3];
    const float* spe = (const float*)d_in[4];
    const float* qw  = (const float*)d_in[5];
    const float* qb  = (const float*)d_in[6];
    const float* kw  = (const float*)d_in[7];
    // d_in[8] = k_b: cancels in softmax (constant per-head shift)
    const float* vw  = (const float*)d_in[9];
    const float* vb  = (const float*)d_in[10];
    const float* ow  = (const float*)d_in[11];
    const float* ob  = (const float*)d_in[12];
    const float* lng = (const float*)d_in[13];
    const float* lnb = (const float*)d_in[14];
    const int*  qidx = (n_in > 15) ? (const int*)d_in[15] : nullptr;

    const int smem_bytes = 256*129*4;   // 132096 -> 1 CTA/SM -> co-residency
    cudaFuncSetAttribute(k_fused, cudaFuncAttributeMaxDynamicSharedMemorySize, smem_bytes);

    k_fused<<<NB, 512, smem_bytes>>>(hf, qe, cpe, tpe, spe, qw, qb, kw,
                                     vw, vb, ow, ob, lng, lnb, qidx,
                                     (float*)d_out);
}

// round 6
// speedup vs baseline: 1.0875x; 1.0875x over previous
#include <cuda_runtime.h>

#define NV 6
#define NT 3
#define NC 256
#define SP 1024
#define NHD 8
#define CHUNK 128
#define NB (NV*NT*8)        // 144 blocks
#define SCALE 0.17677669529663687f
#define LN_EPS 1e-5f
#define NSLOT 8

// ---------------- scratch ----------------------------------------------------
__device__ float g_wq[NC*NHD];          // [c*8+h]
__device__ float g_S8[NSLOT*NHD*NC];    // slotted unnormalized sum_k e*kv
__device__ float g_L8[NSLOT*NHD];       // slotted sum_k e
__device__ float g_t[NC];
__device__ float g_u[NC];

__device__ __forceinline__ float wredsum(float v){
#pragma unroll
    for(int o=16;o;o>>=1) v += __shfl_down_sync(0xffffffffu, v, o);
    return v;
}

// ---------------- K0: per-head wq + zero accumulators ------------------------
__global__ void k_prep(const float* __restrict__ qe, const float* __restrict__ cpe,
                       const float* __restrict__ spe, const float* __restrict__ qw,
                       const float* __restrict__ qb, const float* __restrict__ kw,
                       const int* __restrict__ qidx_p){
    int b = blockIdx.x, tid = threadIdx.x;
    if(b >= 8){
        int z = b - 8;
#pragma unroll
        for(int i=0;i<8;i++) g_S8[z*2048 + i*256 + tid] = 0.f;
        if(tid < NHD) g_L8[z*NHD + tid] = 0.f;
        return;
    }
    int h = b;
    __shared__ __align__(16) float qv[NC];
    __shared__ float qps[32];
    int qidx = qidx_p ? qidx_p[0] : 0;
    qv[tid] = qe[tid] + cpe[qidx*NC + tid] + spe[tid];
    __syncthreads();
    int w = tid >> 5, ln = tid & 31;
    const float4* qv4 = (const float4*)qv;
    float4 x = qv4[ln*2], y = qv4[ln*2+1];
#pragma unroll
    for(int k=0;k<4;k++){
        int j = h*32 + w*4 + k;
        const float4* qwr = (const float4*)(qw + (size_t)j*NC);
        float4 a = qwr[ln*2], b4 = qwr[ln*2+1];
        float d = a.x*x.x + a.y*x.y + a.z*x.z + a.w*x.w
                + b4.x*y.x + b4.y*y.y + b4.z*y.z + b4.w*y.w;
        d = wredsum(d);
        if(ln == 0) qps[w*4+k] = d + qb[j];
    }
    __syncthreads();
    float acc = 0.f;
    const float* kwb = kw + (size_t)(h*32)*NC + tid;
#pragma unroll
    for(int d=0; d<32; d++) acc += qps[d]*kwb[(size_t)d*NC];
    g_wq[tid*NHD + h] = acc * SCALE;
}

// ---------------- K1: main pass (512 threads, MLP-16 staging) ----------------
__global__ __launch_bounds__(512,1)
void k_main(const float* __restrict__ hf, const float* __restrict__ tpe,
            const float* __restrict__ cpe){
    extern __shared__ float tile[];               // [256][129], 132096 B
    __shared__ float pe[NC];
    __shared__ __align__(16) float wq_sm[NC*NHD];
    __shared__ __align__(16) float p_sm[CHUNK*NHD];     // [pos*8+h]
    __shared__ float sred[4*NHD*CHUNK];                 // [q][h][pos]

    int tid = threadIdx.x;
    int b = blockIdx.x;
    int vt = b >> 3, chunk = b & 7;
    int v = vt / NT, t = vt - v*NT;
    int pos = tid & 127, q = tid >> 7;      // q: channel quarter 0..3
    int c0 = q*64;

    if(tid < 256) pe[tid] = tpe[t*NC + tid] + cpe[v*NC + tid];
#pragma unroll
    for(int k=0;k<4;k++) wq_sm[tid + k*512] = g_wq[tid + k*512];
    __syncthreads();

    // -------- stage kv tile: 64 channels/thread, 16 loads in flight ----------
    {
        const float* src = hf + ((size_t)(vt*NC + c0))*SP + chunk*CHUNK + pos;
        float r[16];
#pragma unroll
        for(int bch=0; bch<4; bch++){
#pragma unroll
            for(int j=0;j<16;j++) r[j] = src[(size_t)(bch*16+j)*SP];
#pragma unroll
            for(int j=0;j<16;j++){
                int c = c0 + bch*16 + j;
                tile[c*129 + pos] = r[j] + pe[c];
            }
        }
    }
    __syncthreads();

    // -------- pass 1: per-quarter score partials ----------------------------
    {
        float acc[8];
#pragma unroll
        for(int h=0;h<8;h++) acc[h]=0.f;
        const float4* wq4 = (const float4*)wq_sm;
#pragma unroll 4
        for(int i=0;i<64;i++){
            int c = c0 + i;
            float kv = tile[c*129 + pos];
            float4 w0 = wq4[c*2], w1 = wq4[c*2+1];
            acc[0] += kv*w0.x; acc[1] += kv*w0.y; acc[2] += kv*w0.z; acc[3] += kv*w0.w;
            acc[4] += kv*w1.x; acc[5] += kv*w1.y; acc[6] += kv*w1.z; acc[7] += kv*w1.w;
        }
#pragma unroll
        for(int h=0;h<8;h++) sred[q*1024 + h*128 + pos] = acc[h];
    }
    __syncthreads();

    // -------- scores -> e = exp(s) (|s| << 1, no max shift), local l ---------
    {
        int w = tid >> 5, ln = tid & 31;
        if(w < 8){
            float l = 0.f;
#pragma unroll
            for(int qq=0;qq<4;qq++){
                int p = ln + qq*32;
                float s = sred[w*128+p] + sred[1024+w*128+p]
                        + sred[2048+w*128+p] + sred[3072+w*128+p];
                float e = __expf(s);
                p_sm[p*8 + w] = e;
                l += e;
            }
            l = wredsum(l);
            if(ln == 0) atomicAdd(&g_L8[(b & (NSLOT-1))*NHD + w], l);
        }
    }
    __syncthreads();

    // -------- pass 2: partial[h][c] = sum_pos e*kv ---------------------------
    {
        int grp = tid >> 6, cid = tid & 63;       // 8 groups x 16 positions
        float acc[8][4];
#pragma unroll
        for(int h=0;h<8;h++)
#pragma unroll
            for(int qq=0;qq<4;qq++) acc[h][qq]=0.f;
        const float4* p4 = (const float4*)p_sm;
        int p0 = grp*16;
#pragma unroll 2
        for(int pp=0;pp<16;pp++){
            int p = p0 + pp;
            float4 pa = p4[p*2], pb = p4[p*2+1];
            float pv[8] = {pa.x,pa.y,pa.z,pa.w,pb.x,pb.y,pb.z,pb.w};
            float kvv[4];
#pragma unroll
            for(int qq=0;qq<4;qq++) kvv[qq] = tile[(cid + qq*64)*129 + p];
#pragma unroll
            for(int h=0;h<8;h++)
#pragma unroll
                for(int qq=0;qq<4;qq++) acc[h][qq] += pv[h]*kvv[qq];
        }
        __syncthreads();            // all tile reads done; reuse as staging
#pragma unroll
        for(int h=0;h<8;h++)
#pragma unroll
            for(int qq=0;qq<4;qq++)
                tile[grp*2048 + h*256 + (cid + qq*64)] = acc[h][qq];
    }
    __syncthreads();

    // -------- combine 8 groups, slotted atomic accumulate --------------------
    {
        int slot = b & (NSLOT-1);
#pragma unroll
        for(int k=0;k<4;k++){
            int idx = k*512 + tid;     // idx = h*256 + c
            float s = 0.f;
#pragma unroll
            for(int g=0; g<8; g++) s += tile[g*2048 + idx];
            atomicAdd(&g_S8[slot*2048 + idx], s);
        }
    }
}

// ---------------- K2: slot-reduce + normalize + V-GEMV (64 blocks x 4 rows) --
__global__ __launch_bounds__(512)
void k_t(const float* __restrict__ vw, const float* __restrict__ vb){
    __shared__ __align__(16) float S_sm[NC];
    __shared__ float red16[16];
    int b = blockIdx.x, tid = threadIdx.x;
    int w = tid >> 5, ln = tid & 31;
    int h = b >> 3;                                 // 8 blocks per head
    if(tid < 256){
        float s = 0.f;
#pragma unroll
        for(int r=0;r<NSLOT;r++) s += g_S8[r*2048 + h*256 + tid];
        float L = 0.f;
#pragma unroll
        for(int r=0;r<NSLOT;r++) L += g_L8[r*NHD + h];
        S_sm[tid] = s / L;
    }
    __syncthreads();
    int r = tid >> 7, cid = tid & 127;              // 4 rows, 128 threads each
    int j = b*4 + r;
    float2 S2 = ((const float2*)S_sm)[cid];
    float2 w2 = ((const float2*)(vw + (size_t)j*NC))[cid];
    float part = S2.x*w2.x + S2.y*w2.y;
    part = wredsum(part);
    if(ln == 0) red16[w] = part;
    __syncthreads();
    if(tid < 4){
        float s = red16[tid*4] + red16[tid*4+1] + red16[tid*4+2] + red16[tid*4+3];
        g_t[b*4 + tid] = s + vb[b*4 + tid];
    }
}

// ---------------- K3: O-GEMV (64 blocks x 4 rows) ----------------------------
__global__ __launch_bounds__(512)
void k_u(const float* __restrict__ ow, const float* __restrict__ ob){
    __shared__ __align__(16) float t_sm[NC];
    __shared__ float red16[16];
    int b = blockIdx.x, tid = threadIdx.x;
    int w = tid >> 5, ln = tid & 31;
    if(tid < 256) t_sm[tid] = g_t[tid];
    __syncthreads();
    int r = tid >> 7, cid = tid & 127;
    int j = b*4 + r;
    float2 S2 = ((const float2*)t_sm)[cid];
    float2 w2 = ((const float2*)(ow + (size_t)j*NC))[cid];
    float part = S2.x*w2.x + S2.y*w2.y;
    part = wredsum(part);
    if(ln == 0) red16[w] = part;
    __syncthreads();
    if(tid < 4){
        float s = red16[tid*4] + red16[tid*4+1] + red16[tid*4+2] + red16[tid*4+3];
        g_u[b*4 + tid] = s + ob[b*4 + tid];
    }
}

// ---------------- K4: fused LayerNorm + broadcast ----------------------------
__global__ void k_bcast(const float* __restrict__ lng, const float* __restrict__ lnb,
                        float* __restrict__ out){
    __shared__ float r1[8], r2[8];
    int tid = threadIdx.x, c = blockIdx.x;
    float uv = g_u[tid];
    float s1 = wredsum(uv);
    float s2 = wredsum(uv*uv);
    int w = tid >> 5, ln = tid & 31;
    if(ln == 0){ r1[w] = s1; r2[w] = s2; }
    __syncthreads();
    if(w == 0){
        float a = (ln < 8) ? r1[ln] : 0.f;
        float b = (ln < 8) ? r2[ln] : 0.f;
#pragma unroll
        for(int o=4;o;o>>=1){ a += __shfl_down_sync(0xffffffffu,a,o); b += __shfl_down_sync(0xffffffffu,b,o); }
        if(ln == 0){ r1[0] = a; r2[0] = b; }
    }
    __syncthreads();
    float mu  = r1[0] * (1.f/NC);
    float var = r2[0] * (1.f/NC) - mu*mu;
    float yv = (g_u[c] - mu) * rsqrtf(var + LN_EPS) * lng[c] + lnb[c];
    float4 v = make_float4(yv, yv, yv, yv);
    ((float4*)out)[c*256 + tid] = v;
}

// ---------------- launch -----------------------------------------------------
extern "C" void kernel_launch(void* const* d_in, const int* in_sizes, int n_in,
                              void* d_out, int out_size){
    const float* hf  = (const float*)d_in[0];
    const float* qe  = (const float*)d_in[1];
    const float* cpe = (const float*)d_in[2];
    const float* tpe = (const float*)d_in[3];
    const float* spe = (const float*)d_in[4];
    const float* qw  = (const float*)d_in[5];
    const float* qb  = (const float*)d_in[6];
    const float* kw  = (const float*)d_in[7];
    // d_in[8] = k_b: cancels in softmax (constant per-head shift)
    const float* vw  = (const float*)d_in[9];
    const float* vb  = (const float*)d_in[10];
    const float* ow  = (const float*)d_in[11];
    const float* ob  = (const float*)d_in[12];
    const float* lng = (const float*)d_in[13];
    const float* lnb = (const float*)d_in[14];
    const int*  qidx = (n_in > 15) ? (const int*)d_in[15] : nullptr;

    const int smem_bytes = 256*129*4;   // 132096
    cudaFuncSetAttribute(k_main, cudaFuncAttributeMaxDynamicSharedMemorySize, smem_bytes);

    k_prep <<<16, 256>>>(qe, cpe, spe, qw, qb, kw, qidx);
    k_main <<<NB, 512, smem_bytes>>>(hf, tpe, cpe);
    k_t    <<<64, 512>>>(vw, vb);
    k_u    <<<64, 512>>>(ow, ob);
    k_bcast<<<256, 256>>>(lng, lnb, (float*)d_out);
}